// round 13
// baseline (speedup 1.0000x reference)
#include <cuda_runtime.h>
#include <stdint.h>

// Problem constants
#define Bb    32768
#define Ll    7
#define Tt    6
#define Hh    256
#define TS    5                 // only edges t=0..4 are live
#define MROWS (Bb * TS)         // 163840
#define MCTX  (Bb * Ll)         // 229376

// ---------------- device scratch (static, allocation-free) ----------------
__device__ float g_Edge[(size_t)MROWS * Hh];
__device__ float g_qt  [Bb * Hh];
__device__ float g_inp [Bb * Hh];
__device__ float g_att2[MCTX];
__device__ float g_colmax[Ll];
__device__ float g_colsum[Ll];
__device__ float g_logZ[Ll];
__device__ int   g_rmap[MROWS];
__device__ int   g_hv  [MROWS];
__device__ int   g_cntA;
__device__ int   g_cntB;
__device__ int   g_is64;

typedef unsigned long long u64;

// ---------------- small helpers ----------------
__device__ __forceinline__ u64 pack2(float x, float y) {
    u64 r;
    asm("mov.b64 %0, {%1, %2};" : "=l"(r) : "r"(__float_as_uint(x)), "r"(__float_as_uint(y)));
    return r;
}
__device__ __forceinline__ float2 unpack2(u64 v) {
    unsigned int lo, hi;
    asm("mov.b64 {%0, %1}, %2;" : "=r"(lo), "=r"(hi) : "l"(v));
    float2 f; f.x = __uint_as_float(lo); f.y = __uint_as_float(hi); return f;
}
#define FMA2(acc, a, b) asm("fma.rn.f32x2 %0, %1, %2, %0;" : "+l"(acc) : "l"(a), "l"(b))

__device__ __forceinline__ uint32_t rotl32(uint32_t v, int r) { return (v << r) | (v >> (32 - r)); }

// JAX Threefry-2x32-20, key = (0, 42); partitionable stream, o0^o1 fold
__device__ __forceinline__ void tf2x32(uint32_t x0, uint32_t x1, uint32_t& o0, uint32_t& o1) {
    const uint32_t k0 = 0u, k1 = 42u, k2 = 0u ^ 42u ^ 0x1BD11BDAu;
    x0 += k0; x1 += k1;
#define TFR(r) { x0 += x1; x1 = rotl32(x1, (r)); x1 ^= x0; }
    TFR(13) TFR(15) TFR(26) TFR(6)   x0 += k1; x1 += k2 + 1u;
    TFR(17) TFR(29) TFR(16) TFR(24)  x0 += k2; x1 += k0 + 2u;
    TFR(13) TFR(15) TFR(26) TFR(6)   x0 += k0; x1 += k1 + 3u;
    TFR(17) TFR(29) TFR(16) TFR(24)  x0 += k1; x1 += k2 + 4u;
    TFR(13) TFR(15) TFR(26) TFR(6)   x0 += k2; x1 += k0 + 5u;
#undef TFR
    o0 = x0; o1 = x1;
}
__device__ __forceinline__ uint32_t jax_bits(uint32_t n) {
    uint32_t o0, o1; tf2x32(0u, n, o0, o1); return o0 ^ o1;
}

// ---------------- setup kernels ----------------
__global__ void k_init() { g_cntA = 0; g_cntB = 0; }

__global__ void k_detect(const int* __restrict__ xes) {
    __shared__ int any;
    if (threadIdx.x == 0) any = 0;
    __syncthreads();
    if (xes[2 * threadIdx.x + 1] != 0) any = 1;
    __syncthreads();
    if (threadIdx.x == 0) g_is64 = !any;
}

__global__ void k_map(const int* __restrict__ xes) {
    int bt = blockIdx.x * blockDim.x + threadIdx.x;
    if (bt >= MROWS) return;
    int b = bt / TS, t = bt - b * TS;
    int base = (b * Tt + t) * 3;
    int s = g_is64 ? 2 : 1;
    int h  = xes[(base + 0) * s];
    int v  = xes[(base + 1) * s];
    int tt = xes[(base + 2) * s];
    int g;
    if (tt == 0) g = atomicAdd(&g_cntA, 1);
    else         g = MROWS - 1 - atomicAdd(&g_cntB, 1);
    g_rmap[g] = bt;
    g_hv[g]   = h | (v << 8);
}

// ---------------- edge GEMM: fused gather, paired-row 16x8, dup-B smem ----
// 128 rows x 256 cols per block, 256 threads, K = 512 (h half then v half).
__global__ void __launch_bounds__(256, 1) k_edges(const float* __restrict__ enc,
                                                  const float* __restrict__ Wh,
                                                  const float* __restrict__ Wv,
                                                  const float* __restrict__ Wsh,
                                                  const float* __restrict__ Wsv) {
    const int row0 = blockIdx.x * 128;
    __shared__ __align__(16) float As[16][132];
    __shared__ __align__(16) u64   Bs2[16][260];   // (b,b) dup pairs
    __shared__ const float* rpH[128];
    __shared__ const float* rpV[128];
    __shared__ int sbt[128];

    const int tid = threadIdx.x;
    if (tid < 128) {
        int g = row0 + tid;
        int bt = g_rmap[g];
        int hv = g_hv[g];
        int b = bt / TS;
        sbt[tid] = bt;
        rpH[tid] = enc + (size_t)(b * Ll + (hv & 255)) * 256;
        rpV[tid] = enc + (size_t)(b * Ll + (hv >> 8)) * 256;
    }
    __syncthreads();

    const int bound = g_cntA;
    const int tx = tid & 31, ty = tid >> 5;       // tx: 8 cols (256), ty: 16 rows (128)
    const int r0 = tid >> 2, ak = (tid & 3) * 4;  // loader mapping

    for (int pass = 0; pass < 2; pass++) {
        if (pass == 0 && row0 >= bound) continue;
        if (pass == 1 && row0 + 128 <= bound) continue;
        const float* WA = pass ? Wsh : Wh;
        const float* WB = pass ? Wsv : Wv;

        u64 acc[8][8];   // [row-pair][col]
#pragma unroll
        for (int i = 0; i < 8; i++)
#pragma unroll
            for (int j = 0; j < 8; j++) acc[i][j] = 0ull;

        __syncthreads();   // guard smem reuse across passes

        // preload kk = 0
        float4 a_st0 = *(const float4*)(rpH[r0] + ak);
        float4 a_st1 = *(const float4*)(rpH[r0 + 64] + ak);
        float4 b_st[4];
#pragma unroll
        for (int j = 0; j < 4; j++)
            b_st[j] = *(const float4*)(WA + (size_t)(r0 + j * 64) * 256 + ak);

        for (int kk = 0; kk < 512; kk += 16) {
            As[ak + 0][r0] = a_st0.x; As[ak + 1][r0] = a_st0.y;
            As[ak + 2][r0] = a_st0.z; As[ak + 3][r0] = a_st0.w;
            As[ak + 0][r0 + 64] = a_st1.x; As[ak + 1][r0 + 64] = a_st1.y;
            As[ak + 2][r0 + 64] = a_st1.z; As[ak + 3][r0 + 64] = a_st1.w;
#pragma unroll
            for (int j = 0; j < 4; j++) {
                int n = r0 + j * 64;
                Bs2[ak + 0][n] = pack2(b_st[j].x, b_st[j].x);
                Bs2[ak + 1][n] = pack2(b_st[j].y, b_st[j].y);
                Bs2[ak + 2][n] = pack2(b_st[j].z, b_st[j].z);
                Bs2[ak + 3][n] = pack2(b_st[j].w, b_st[j].w);
            }
            __syncthreads();

            int kn = kk + 16;
            if (kn < 512) {
                int off = (kn & 255) + ak;
                const float* const* rp = (kn < 256) ? rpH : rpV;
                a_st0 = *(const float4*)(rp[r0] + off);
                a_st1 = *(const float4*)(rp[r0 + 64] + off);
                const float* Wp = (kn < 256) ? WA : WB;
#pragma unroll
                for (int j = 0; j < 4; j++)
                    b_st[j] = *(const float4*)(Wp + (size_t)(r0 + j * 64) * 256 + off);
            }

#pragma unroll
            for (int p = 0; p < 16; p++) {
                // A row pairs: 16 floats -> 8 u64 pairs via 4x LDS.128
                ulonglong2 tA0 = *(const ulonglong2*)&As[p][ty * 16];
                ulonglong2 tA1 = *(const ulonglong2*)&As[p][ty * 16 + 4];
                ulonglong2 tA2 = *(const ulonglong2*)&As[p][ty * 16 + 8];
                ulonglong2 tA3 = *(const ulonglong2*)&As[p][ty * 16 + 12];
                u64 aa[8] = {tA0.x, tA0.y, tA1.x, tA1.y, tA2.x, tA2.y, tA3.x, tA3.y};
                // B dup pairs: 8 u64 via 4x LDS.128
                ulonglong2 tB0 = *(const ulonglong2*)&Bs2[p][tx * 8];
                ulonglong2 tB1 = *(const ulonglong2*)&Bs2[p][tx * 8 + 2];
                ulonglong2 tB2 = *(const ulonglong2*)&Bs2[p][tx * 8 + 4];
                ulonglong2 tB3 = *(const ulonglong2*)&Bs2[p][tx * 8 + 6];
                u64 bb[8] = {tB0.x, tB0.y, tB1.x, tB1.y, tB2.x, tB2.y, tB3.x, tB3.y};
#pragma unroll
                for (int i = 0; i < 8; i++)
#pragma unroll
                    for (int j = 0; j < 8; j++) FMA2(acc[i][j], aa[i], bb[j]);
            }
            __syncthreads();
        }

#pragma unroll
        for (int i = 0; i < 8; i++) {
            int r_lo = ty * 16 + 2 * i;
            float clo[8], chi[8];
#pragma unroll
            for (int j = 0; j < 8; j++) {
                float2 f = unpack2(acc[i][j]);
                clo[j] = f.x; chi[j] = f.y;
            }
            int g_lo = row0 + r_lo;
            bool ok_lo = (pass == 0) ? (g_lo < bound) : (g_lo >= bound);
            bool ok_hi = (pass == 0) ? (g_lo + 1 < bound) : (g_lo + 1 >= bound);
            if (ok_lo) {
                float* o = g_Edge + (size_t)sbt[r_lo] * 256 + tx * 8;
                *(float4*)(o)     = make_float4(clo[0], clo[1], clo[2], clo[3]);
                *(float4*)(o + 4) = make_float4(clo[4], clo[5], clo[6], clo[7]);
            }
            if (ok_hi) {
                float* o = g_Edge + (size_t)sbt[r_lo + 1] * 256 + tx * 8;
                *(float4*)(o)     = make_float4(chi[0], chi[1], chi[2], chi[3]);
                *(float4*)(o + 4) = make_float4(chi[4], chi[5], chi[6], chi[7]);
            }
        }
    }
}

// ---------------- S GEMM fused with subtree-max + qt, paired rows ---------
// 160 rows x 128 cols, 256 threads; 10-row microtile = 5 row pairs.
__global__ void __launch_bounds__(256) k_subq(const float* __restrict__ We) {
    const int row0 = blockIdx.x * 160;
    const int col0 = blockIdx.y * 128;
    __shared__ __align__(16) float As[16][164];
    __shared__ __align__(16) u64   Bs2[16][132];
    const int tid = threadIdx.x;
    const int tx = tid & 15, ty = tid >> 4;   // tx: 8 cols (128), ty: 10 rows (160)

    u64 acc[5][8];
#pragma unroll
    for (int i = 0; i < 5; i++)
#pragma unroll
        for (int j = 0; j < 8; j++) acc[i][j] = 0ull;

    float4 a_st[3], b_st[2];
#pragma unroll
    for (int i = 0; i < 3; i++) {
        int idx = tid + i * 256;
        if (idx < 640) {
            int m = idx >> 2, kq = (idx & 3) * 4;
            a_st[i] = *(const float4*)(g_Edge + (size_t)(row0 + m) * 256 + kq);
        }
    }
#pragma unroll
    for (int i = 0; i < 2; i++) {
        int idx = tid + i * 256;
        int n = idx >> 2, kq = (idx & 3) * 4;
        b_st[i] = *(const float4*)(We + (size_t)(col0 + n) * 256 + kq);
    }

    for (int kk = 0; kk < 256; kk += 16) {
#pragma unroll
        for (int i = 0; i < 3; i++) {
            int idx = tid + i * 256;
            if (idx < 640) {
                int m = idx >> 2, kq = (idx & 3) * 4;
                As[kq + 0][m] = a_st[i].x; As[kq + 1][m] = a_st[i].y;
                As[kq + 2][m] = a_st[i].z; As[kq + 3][m] = a_st[i].w;
            }
        }
#pragma unroll
        for (int i = 0; i < 2; i++) {
            int idx = tid + i * 256;
            int n = idx >> 2, kq = (idx & 3) * 4;
            Bs2[kq + 0][n] = pack2(b_st[i].x, b_st[i].x);
            Bs2[kq + 1][n] = pack2(b_st[i].y, b_st[i].y);
            Bs2[kq + 2][n] = pack2(b_st[i].z, b_st[i].z);
            Bs2[kq + 3][n] = pack2(b_st[i].w, b_st[i].w);
        }
        __syncthreads();

        int kn = kk + 16;
        if (kn < 256) {
#pragma unroll
            for (int i = 0; i < 3; i++) {
                int idx = tid + i * 256;
                if (idx < 640) {
                    int m = idx >> 2, kq = (idx & 3) * 4;
                    a_st[i] = *(const float4*)(g_Edge + (size_t)(row0 + m) * 256 + kn + kq);
                }
            }
#pragma unroll
            for (int i = 0; i < 2; i++) {
                int idx = tid + i * 256;
                int n = idx >> 2, kq = (idx & 3) * 4;
                b_st[i] = *(const float4*)(We + (size_t)(col0 + n) * 256 + kn + kq);
            }
        }

#pragma unroll
        for (int p = 0; p < 16; p++) {
            // A: 10 floats = 5 pairs via LDS.64 (8B-aligned)
            u64 aa[5];
            const u64* ap = (const u64*)&As[p][ty * 10];
#pragma unroll
            for (int i = 0; i < 5; i++) aa[i] = ap[i];
            ulonglong2 tB0 = *(const ulonglong2*)&Bs2[p][tx * 8];
            ulonglong2 tB1 = *(const ulonglong2*)&Bs2[p][tx * 8 + 2];
            ulonglong2 tB2 = *(const ulonglong2*)&Bs2[p][tx * 8 + 4];
            ulonglong2 tB3 = *(const ulonglong2*)&Bs2[p][tx * 8 + 6];
            u64 bb[8] = {tB0.x, tB0.y, tB1.x, tB1.y, tB2.x, tB2.y, tB3.x, tB3.y};
#pragma unroll
            for (int i = 0; i < 5; i++)
#pragma unroll
                for (int j = 0; j < 8; j++) FMA2(acc[i][j], aa[i], bb[j]);
        }
        __syncthreads();
    }

    // epilogue: rows g = pair(g>>1), half(g&1); groups rows 0-4 and 5-9
    float mx0[8], mx1[8];
#pragma unroll
    for (int j = 0; j < 8; j++) { mx0[j] = 0.f; mx1[j] = 0.f; }
#pragma unroll
    for (int g = 0; g < 10; g++) {
        int i = g >> 1, h = g & 1;
#pragma unroll
        for (int j = 0; j < 8; j++) {
            float2 f = unpack2(acc[i][j]);
            float v = h ? f.y : f.x;
            if (g < 5) mx0[j] = fmaxf(mx0[j], v);
            else       mx1[j] = fmaxf(mx1[j], v);
        }
    }
#pragma unroll
    for (int grp = 0; grp < 2; grp++) {
        int gr = row0 + ty * 10 + grp * 5;    // = b*5
        int b = gr / 5;
        const float* mx = grp ? mx1 : mx0;
        const float* e4 = g_Edge + (size_t)(gr + 4) * 256 + col0 + tx * 8;
        float4 e0 = *(const float4*)(e4);
        float4 e1 = *(const float4*)(e4 + 4);
        float q[8];
        q[0] = fmaxf(e0.x + mx[0], 0.f); q[1] = fmaxf(e0.y + mx[1], 0.f);
        q[2] = fmaxf(e0.z + mx[2], 0.f); q[3] = fmaxf(e0.w + mx[3], 0.f);
        q[4] = fmaxf(e1.x + mx[4], 0.f); q[5] = fmaxf(e1.y + mx[5], 0.f);
        q[6] = fmaxf(e1.z + mx[6], 0.f); q[7] = fmaxf(e1.w + mx[7], 0.f);
        float* o = g_qt + (size_t)b * 256 + col0 + tx * 8;
        *(float4*)(o)     = make_float4(q[0], q[1], q[2], q[3]);
        *(float4*)(o + 4) = make_float4(q[4], q[5], q[6], q[7]);
    }
}

// ---------------- inp = qt @ W_in^T + b_in, paired rows -------------------
__global__ void __launch_bounds__(256) k_inp(const float* __restrict__ Wi,
                                             const float* __restrict__ bi) {
    const int row0 = blockIdx.x * 128;
    const int col0 = blockIdx.y * 128;
    __shared__ __align__(16) float As[16][132];
    __shared__ __align__(16) u64   Bs2[16][132];
    const int tid = threadIdx.x;
    const int tx = tid & 15, ty = tid >> 4;

    u64 acc[4][8];
#pragma unroll
    for (int i = 0; i < 4; i++)
#pragma unroll
        for (int j = 0; j < 8; j++) acc[i][j] = 0ull;

    float4 a_st[2], b_st[2];
#pragma unroll
    for (int i = 0; i < 2; i++) {
        int idx = tid + i * 256;
        int m = idx >> 2, kq = (idx & 3) * 4;
        a_st[i] = *(const float4*)(g_qt + (size_t)(row0 + m) * 256 + kq);
        b_st[i] = *(const float4*)(Wi + (size_t)(col0 + m) * 256 + kq);
    }

    for (int kk = 0; kk < 256; kk += 16) {
#pragma unroll
        for (int i = 0; i < 2; i++) {
            int idx = tid + i * 256;
            int m = idx >> 2, kq = (idx & 3) * 4;
            As[kq + 0][m] = a_st[i].x; As[kq + 1][m] = a_st[i].y;
            As[kq + 2][m] = a_st[i].z; As[kq + 3][m] = a_st[i].w;
            Bs2[kq + 0][m] = pack2(b_st[i].x, b_st[i].x);
            Bs2[kq + 1][m] = pack2(b_st[i].y, b_st[i].y);
            Bs2[kq + 2][m] = pack2(b_st[i].z, b_st[i].z);
            Bs2[kq + 3][m] = pack2(b_st[i].w, b_st[i].w);
        }
        __syncthreads();

        int kn = kk + 16;
        if (kn < 256) {
#pragma unroll
            for (int i = 0; i < 2; i++) {
                int idx = tid + i * 256;
                int m = idx >> 2, kq = (idx & 3) * 4;
                a_st[i] = *(const float4*)(g_qt + (size_t)(row0 + m) * 256 + kn + kq);
                b_st[i] = *(const float4*)(Wi + (size_t)(col0 + m) * 256 + kn + kq);
            }
        }

#pragma unroll
        for (int p = 0; p < 16; p++) {
            ulonglong2 tA0 = *(const ulonglong2*)&As[p][ty * 8];
            ulonglong2 tA1 = *(const ulonglong2*)&As[p][ty * 8 + 4];
            u64 aa[4] = {tA0.x, tA0.y, tA1.x, tA1.y};
            ulonglong2 tB0 = *(const ulonglong2*)&Bs2[p][tx * 8];
            ulonglong2 tB1 = *(const ulonglong2*)&Bs2[p][tx * 8 + 2];
            ulonglong2 tB2 = *(const ulonglong2*)&Bs2[p][tx * 8 + 4];
            ulonglong2 tB3 = *(const ulonglong2*)&Bs2[p][tx * 8 + 6];
            u64 bb[8] = {tB0.x, tB0.y, tB1.x, tB1.y, tB2.x, tB2.y, tB3.x, tB3.y};
#pragma unroll
            for (int i = 0; i < 4; i++)
#pragma unroll
                for (int j = 0; j < 8; j++) FMA2(acc[i][j], aa[i], bb[j]);
        }
        __syncthreads();
    }

#pragma unroll
    for (int r = 0; r < 8; r++) {
        int i = r >> 1, h = r & 1;
        float c[8];
#pragma unroll
        for (int j = 0; j < 8; j++) {
            float2 f = unpack2(acc[i][j]);
            c[j] = h ? f.y : f.x;
        }
        const float* bp2 = bi + col0 + tx * 8;
#pragma unroll
        for (int j = 0; j < 8; j++) c[j] += bp2[j];
        float* o = g_inp + (size_t)(row0 + ty * 8 + r) * 256 + col0 + tx * 8;
        *(float4*)(o)     = make_float4(c[0], c[1], c[2], c[3]);
        *(float4*)(o + 4) = make_float4(c[4], c[5], c[6], c[7]);
    }
}

// ---------------- ctx GEMM fused with att2: paired-row 16x8 ---------------
__global__ void __launch_bounds__(256, 1) k_ctx(const float* __restrict__ A,
                                                const float* __restrict__ W,
                                                const float* __restrict__ bias,
                                                const float* __restrict__ Vv,
                                                const int* __restrict__ mask) {
    const int row0 = blockIdx.x * 128;
    __shared__ __align__(16) float As[16][132];
    __shared__ __align__(16) u64   Bs2[16][260];
    const int tid = threadIdx.x;
    const int tx = tid & 31, ty = tid >> 5;
    const int r0 = tid >> 2, ak = (tid & 3) * 4;

    u64 acc[8][8];
#pragma unroll
    for (int i = 0; i < 8; i++)
#pragma unroll
        for (int j = 0; j < 8; j++) acc[i][j] = 0ull;

    float4 a_st0 = *(const float4*)(A + (size_t)(row0 + r0) * 256 + ak);
    float4 a_st1 = *(const float4*)(A + (size_t)(row0 + r0 + 64) * 256 + ak);
    float4 b_st[4];
#pragma unroll
    for (int j = 0; j < 4; j++)
        b_st[j] = *(const float4*)(W + (size_t)(r0 + j * 64) * 256 + ak);

    for (int kk = 0; kk < 256; kk += 16) {
        As[ak + 0][r0] = a_st0.x; As[ak + 1][r0] = a_st0.y;
        As[ak + 2][r0] = a_st0.z; As[ak + 3][r0] = a_st0.w;
        As[ak + 0][r0 + 64] = a_st1.x; As[ak + 1][r0 + 64] = a_st1.y;
        As[ak + 2][r0 + 64] = a_st1.z; As[ak + 3][r0 + 64] = a_st1.w;
#pragma unroll
        for (int j = 0; j < 4; j++) {
            int n = r0 + j * 64;
            Bs2[ak + 0][n] = pack2(b_st[j].x, b_st[j].x);
            Bs2[ak + 1][n] = pack2(b_st[j].y, b_st[j].y);
            Bs2[ak + 2][n] = pack2(b_st[j].z, b_st[j].z);
            Bs2[ak + 3][n] = pack2(b_st[j].w, b_st[j].w);
        }
        __syncthreads();

        int kn = kk + 16;
        if (kn < 256) {
            a_st0 = *(const float4*)(A + (size_t)(row0 + r0) * 256 + kn + ak);
            a_st1 = *(const float4*)(A + (size_t)(row0 + r0 + 64) * 256 + kn + ak);
#pragma unroll
            for (int j = 0; j < 4; j++)
                b_st[j] = *(const float4*)(W + (size_t)(r0 + j * 64) * 256 + kn + ak);
        }

#pragma unroll
        for (int p = 0; p < 16; p++) {
            ulonglong2 tA0 = *(const ulonglong2*)&As[p][ty * 16];
            ulonglong2 tA1 = *(const ulonglong2*)&As[p][ty * 16 + 4];
            ulonglong2 tA2 = *(const ulonglong2*)&As[p][ty * 16 + 8];
            ulonglong2 tA3 = *(const ulonglong2*)&As[p][ty * 16 + 12];
            u64 aa[8] = {tA0.x, tA0.y, tA1.x, tA1.y, tA2.x, tA2.y, tA3.x, tA3.y};
            ulonglong2 tB0 = *(const ulonglong2*)&Bs2[p][tx * 8];
            ulonglong2 tB1 = *(const ulonglong2*)&Bs2[p][tx * 8 + 2];
            ulonglong2 tB2 = *(const ulonglong2*)&Bs2[p][tx * 8 + 4];
            ulonglong2 tB3 = *(const ulonglong2*)&Bs2[p][tx * 8 + 6];
            u64 bb[8] = {tB0.x, tB0.y, tB1.x, tB1.y, tB2.x, tB2.y, tB3.x, tB3.y};
#pragma unroll
            for (int i = 0; i < 8; i++)
#pragma unroll
                for (int j = 0; j < 8; j++) FMA2(acc[i][j], aa[i], bb[j]);
        }
        __syncthreads();
    }

    float bc[8], vv[8];
#pragma unroll
    for (int j = 0; j < 8; j++) { bc[j] = bias[tx * 8 + j]; vv[j] = Vv[tx * 8 + j]; }

#pragma unroll
    for (int r = 0; r < 16; r++) {
        int i = r >> 1, h = r & 1;
        int m = row0 + ty * 16 + r;
        int b = m / Ll;
        const float* ip = g_inp + (size_t)b * 256 + tx * 8;
        float s = 0.f;
#pragma unroll
        for (int j = 0; j < 8; j++) {
            float2 f = unpack2(acc[i][j]);
            float cf = h ? f.y : f.x;
            s += vv[j] * tanhf(ip[j] + (cf + bc[j]));
        }
#pragma unroll
        for (int o = 16; o > 0; o >>= 1) s += __shfl_xor_sync(0xffffffffu, s, o);
        if (tx == 0) {
            if (mask[m] == 0) s = -1000000000.0f;
            g_att2[m] = 10.0f * tanhf(s);
        }
    }
}

// ---------------- per-column softmax stats over batch axis ----------------
__global__ void k_colred() {
    const int l = blockIdx.x;
    __shared__ float red[256];
    float mx = __int_as_float(0xff800000);
    for (int b = threadIdx.x; b < Bb; b += 256) mx = fmaxf(mx, g_att2[b * Ll + l]);
    red[threadIdx.x] = mx; __syncthreads();
    for (int o = 128; o > 0; o >>= 1) {
        if (threadIdx.x < o) red[threadIdx.x] = fmaxf(red[threadIdx.x], red[threadIdx.x + o]);
        __syncthreads();
    }
    mx = red[0]; __syncthreads();
    float sum = 0.f;
    for (int b = threadIdx.x; b < Bb; b += 256) sum += expf(g_att2[b * Ll + l] - mx);
    red[threadIdx.x] = sum; __syncthreads();
    for (int o = 128; o > 0; o >>= 1) {
        if (threadIdx.x < o) red[threadIdx.x] += red[threadIdx.x + o];
        __syncthreads();
    }
    if (threadIdx.x == 0) {
        g_colmax[l] = mx;
        g_colsum[l] = red[0];
        g_logZ[l]   = mx + logf(red[0]);
    }
}

// ---------------- Gumbel-argmax + p + new_mask ----------------------------
__global__ void k_final(const int* __restrict__ mask, float* __restrict__ out) {
    int b = blockIdx.x * blockDim.x + threadIdx.x;
    if (b >= Bb) return;
    const float TINY = 1.17549435e-38f;
    float best = __int_as_float(0xff800000);
    int idx = 0;
    float a2[Ll];
#pragma unroll
    for (int l = 0; l < Ll; l++) {
        float a = g_att2[b * Ll + l];
        a2[l] = a;
        float la = a - g_logZ[l];
        uint32_t bits = jax_bits((uint32_t)(b * Ll + l));
        float fl = __uint_as_float((bits >> 9) | 0x3F800000u) - 1.0f;
        float u  = fmaxf(TINY, fl + TINY);
        float g  = -logf(-logf(u));
        float s  = la + g;
        if (s > best) { best = s; idx = l; }
    }
    float p = expf(a2[idx] - g_colmax[idx]) / g_colsum[idx];
    out[b]      = (float)idx;
    out[Bb + b] = p;
#pragma unroll
    for (int l = 0; l < Ll; l++)
        out[2 * Bb + b * Ll + l] = (float)(mask[b * Ll + l] - (l == idx ? 1 : 0));
}

// ---------------- launcher ----------------
extern "C" void kernel_launch(void* const* d_in, const int* in_sizes, int n_in,
                              void* d_out, int out_size) {
    const float* enc    = (const float*)d_in[0];
    const int*   xes    = (const int*)  d_in[1];
    const int*   mask   = (const int*)  d_in[2];
    const float* W_h    = (const float*)d_in[3];
    const float* W_v    = (const float*)d_in[4];
    const float* Ws_h   = (const float*)d_in[5];
    const float* Ws_v   = (const float*)d_in[6];
    const float* W_edge = (const float*)d_in[7];
    const float* W_in   = (const float*)d_in[8];
    const float* b_in   = (const float*)d_in[9];
    const float* W_ctx  = (const float*)d_in[10];
    const float* b_ctx  = (const float*)d_in[11];
    const float* Vv     = (const float*)d_in[12];
    float* out = (float*)d_out;

    k_init<<<1, 1>>>();
    k_detect<<<1, 128>>>(xes);
    k_map<<<(MROWS + 255) / 256, 256>>>(xes);

    k_edges<<<MROWS / 128, 256>>>(enc, W_h, W_v, Ws_h, Ws_v);
    k_subq<<<dim3(MROWS / 160, 2), 256>>>(W_edge);
    k_inp<<<dim3(Bb / 128, 2), 256>>>(W_in, b_in);
    k_ctx<<<MCTX / 128, 256>>>(enc, W_ctx, b_ctx, Vv, mask);
    k_colred<<<Ll, 256>>>();
    k_final<<<(Bb + 255) / 256, 256>>>(mask, out);
}

// round 14
// speedup vs baseline: 3.0282x; 3.0282x over previous
#include <cuda_runtime.h>
#include <stdint.h>

// Problem constants
#define Bb    32768
#define Ll    7
#define Tt    6
#define Hh    256
#define TS    5                 // only edges t=0..4 are live
#define MROWS (Bb * TS)         // 163840
#define MCTX  (Bb * Ll)         // 229376

// ---------------- device scratch (static, allocation-free) ----------------
__device__ float g_Edge[(size_t)MROWS * Hh];
__device__ float g_qt  [Bb * Hh];
__device__ float g_inp [Bb * Hh];
__device__ float g_att2[MCTX];
__device__ float g_colmax[Ll];
__device__ float g_colsum[Ll];
__device__ float g_logZ[Ll];
__device__ int   g_rmap[MROWS];
__device__ int   g_hv  [MROWS];
__device__ int   g_cntA;
__device__ int   g_cntB;
__device__ int   g_is64;

typedef unsigned long long u64;

// ---------------- small helpers ----------------
__device__ __forceinline__ u64 pack2(float x, float y) {
    u64 r;
    asm("mov.b64 %0, {%1, %2};" : "=l"(r) : "r"(__float_as_uint(x)), "r"(__float_as_uint(y)));
    return r;
}
__device__ __forceinline__ float2 unpack2(u64 v) {
    unsigned int lo, hi;
    asm("mov.b64 {%0, %1}, %2;" : "=r"(lo), "=r"(hi) : "l"(v));
    float2 f; f.x = __uint_as_float(lo); f.y = __uint_as_float(hi); return f;
}
#define FMA2(acc, a, b) asm("fma.rn.f32x2 %0, %1, %2, %0;" : "+l"(acc) : "l"(a), "l"(b))

__device__ __forceinline__ uint32_t rotl32(uint32_t v, int r) { return (v << r) | (v >> (32 - r)); }

// JAX Threefry-2x32-20, key = (0, 42); partitionable stream, o0^o1 fold
__device__ __forceinline__ void tf2x32(uint32_t x0, uint32_t x1, uint32_t& o0, uint32_t& o1) {
    const uint32_t k0 = 0u, k1 = 42u, k2 = 0u ^ 42u ^ 0x1BD11BDAu;
    x0 += k0; x1 += k1;
#define TFR(r) { x0 += x1; x1 = rotl32(x1, (r)); x1 ^= x0; }
    TFR(13) TFR(15) TFR(26) TFR(6)   x0 += k1; x1 += k2 + 1u;
    TFR(17) TFR(29) TFR(16) TFR(24)  x0 += k2; x1 += k0 + 2u;
    TFR(13) TFR(15) TFR(26) TFR(6)   x0 += k0; x1 += k1 + 3u;
    TFR(17) TFR(29) TFR(16) TFR(24)  x0 += k1; x1 += k2 + 4u;
    TFR(13) TFR(15) TFR(26) TFR(6)   x0 += k2; x1 += k0 + 5u;
#undef TFR
    o0 = x0; o1 = x1;
}
__device__ __forceinline__ uint32_t jax_bits(uint32_t n) {
    uint32_t o0, o1; tf2x32(0u, n, o0, o1); return o0 ^ o1;
}

// ---------------- setup kernels ----------------
__global__ void k_init() { g_cntA = 0; g_cntB = 0; }

__global__ void k_detect(const int* __restrict__ xes) {
    __shared__ int any;
    if (threadIdx.x == 0) any = 0;
    __syncthreads();
    if (xes[2 * threadIdx.x + 1] != 0) any = 1;
    __syncthreads();
    if (threadIdx.x == 0) g_is64 = !any;
}

__global__ void k_map(const int* __restrict__ xes) {
    int bt = blockIdx.x * blockDim.x + threadIdx.x;
    if (bt >= MROWS) return;
    int b = bt / TS, t = bt - b * TS;
    int base = (b * Tt + t) * 3;
    int s = g_is64 ? 2 : 1;
    int h  = xes[(base + 0) * s];
    int v  = xes[(base + 1) * s];
    int tt = xes[(base + 2) * s];
    int g;
    if (tt == 0) g = atomicAdd(&g_cntA, 1);
    else         g = MROWS - 1 - atomicAdd(&g_cntB, 1);
    g_rmap[g] = bt;
    g_hv[g]   = h | (v << 8);
}

// ---------------- edge GEMM: fused gather, 16x8, dup-A broadcast smem -----
// 128 rows x 256 cols per block, 256 threads, K = 512 (h half then v half).
// A stored as (a,a) u64 pairs; warp reads A by broadcast (ty uniform in warp).
// B stays float; pairs read directly as u64 (consecutive floats), 32B/lane.
__global__ void __launch_bounds__(256, 1) k_edges(const float* __restrict__ enc,
                                                  const float* __restrict__ Wh,
                                                  const float* __restrict__ Wv,
                                                  const float* __restrict__ Wsh,
                                                  const float* __restrict__ Wsv) {
    const int row0 = blockIdx.x * 128;
    __shared__ __align__(16) u64   As2[16][130];   // (a,a) dup pairs, row 1040B (16B-mult)
    __shared__ __align__(16) float Bs[16][260];
    __shared__ const float* rpH[128];
    __shared__ const float* rpV[128];
    __shared__ int sbt[128];

    const int tid = threadIdx.x;
    if (tid < 128) {
        int g = row0 + tid;
        int bt = g_rmap[g];
        int hv = g_hv[g];
        int b = bt / TS;
        sbt[tid] = bt;
        rpH[tid] = enc + (size_t)(b * Ll + (hv & 255)) * 256;
        rpV[tid] = enc + (size_t)(b * Ll + (hv >> 8)) * 256;
    }
    __syncthreads();

    const int bound = g_cntA;
    const int tx = tid & 31, ty = tid >> 5;       // tx: 8 cols (256), ty: 16 rows (128)
    const int r0 = tid >> 2, ak = (tid & 3) * 4;  // loader mapping

    for (int pass = 0; pass < 2; pass++) {
        if (pass == 0 && row0 >= bound) continue;
        if (pass == 1 && row0 + 128 <= bound) continue;
        const float* WA = pass ? Wsh : Wh;
        const float* WB = pass ? Wsv : Wv;

        u64 acc[16][4];
#pragma unroll
        for (int i = 0; i < 16; i++)
#pragma unroll
            for (int j = 0; j < 4; j++) acc[i][j] = 0ull;

        // preload kk = 0
        float4 a_st0 = *(const float4*)(rpH[r0] + ak);
        float4 a_st1 = *(const float4*)(rpH[r0 + 64] + ak);
        float4 b_st[4];
#pragma unroll
        for (int j = 0; j < 4; j++)
            b_st[j] = *(const float4*)(WA + (size_t)(r0 + j * 64) * 256 + ak);

        for (int kk = 0; kk < 512; kk += 16) {
            __syncthreads();
            As2[ak + 0][r0] = pack2(a_st0.x, a_st0.x);
            As2[ak + 1][r0] = pack2(a_st0.y, a_st0.y);
            As2[ak + 2][r0] = pack2(a_st0.z, a_st0.z);
            As2[ak + 3][r0] = pack2(a_st0.w, a_st0.w);
            As2[ak + 0][r0 + 64] = pack2(a_st1.x, a_st1.x);
            As2[ak + 1][r0 + 64] = pack2(a_st1.y, a_st1.y);
            As2[ak + 2][r0 + 64] = pack2(a_st1.z, a_st1.z);
            As2[ak + 3][r0 + 64] = pack2(a_st1.w, a_st1.w);
#pragma unroll
            for (int j = 0; j < 4; j++) {
                int n = r0 + j * 64;
                Bs[ak + 0][n] = b_st[j].x; Bs[ak + 1][n] = b_st[j].y;
                Bs[ak + 2][n] = b_st[j].z; Bs[ak + 3][n] = b_st[j].w;
            }
            __syncthreads();

            int kn = kk + 16;
            if (kn < 512) {
                int off = (kn & 255) + ak;
                const float* const* rp = (kn < 256) ? rpH : rpV;
                a_st0 = *(const float4*)(rp[r0] + off);
                a_st1 = *(const float4*)(rp[r0 + 64] + off);
                const float* Wp = (kn < 256) ? WA : WB;
#pragma unroll
                for (int j = 0; j < 4; j++)
                    b_st[j] = *(const float4*)(Wp + (size_t)(r0 + j * 64) * 256 + off);
            }

#pragma unroll
            for (int p = 0; p < 16; p++) {
                // A: 8x LDS.128, all lanes in warp same address (broadcast)
                const ulonglong2* ap = (const ulonglong2*)&As2[p][ty * 16];
                u64 aa[16];
#pragma unroll
                for (int i = 0; i < 8; i++) {
                    ulonglong2 t = ap[i];
                    aa[2 * i] = t.x; aa[2 * i + 1] = t.y;
                }
                // B: 2x LDS.128 at 32B/lane stride (conflict-free float4 pattern)
                const ulonglong2* bp = (const ulonglong2*)&Bs[p][tx * 8];
                ulonglong2 tb0 = bp[0], tb1 = bp[1];
                u64 bb[4] = {tb0.x, tb0.y, tb1.x, tb1.y};
#pragma unroll
                for (int i = 0; i < 16; i++)
#pragma unroll
                    for (int j = 0; j < 4; j++) FMA2(acc[i][j], aa[i], bb[j]);
            }
        }

#pragma unroll
        for (int i = 0; i < 16; i++) {
            int r = ty * 16 + i;
            int g = row0 + r;
            bool ok = (pass == 0) ? (g < bound) : (g >= bound);
            if (ok) {
                float c[8];
#pragma unroll
                for (int j = 0; j < 4; j++) {
                    float2 f = unpack2(acc[i][j]);
                    c[2 * j] = f.x; c[2 * j + 1] = f.y;
                }
                float* o = g_Edge + (size_t)sbt[r] * 256 + tx * 8;
                *(float4*)(o)     = make_float4(c[0], c[1], c[2], c[3]);
                *(float4*)(o + 4) = make_float4(c[4], c[5], c[6], c[7]);
            }
        }
    }
}

// ---------------- S GEMM fused with subtree-max + qt (R8 + direct-B) ------
__global__ void __launch_bounds__(256) k_subq(const float* __restrict__ We) {
    const int row0 = blockIdx.x * 160;
    const int col0 = blockIdx.y * 128;
    __shared__ __align__(16) float As[16][164];
    __shared__ __align__(16) float Bs[16][132];
    const int tid = threadIdx.x;
    const int tx = tid & 15, ty = tid >> 4;   // tx: 8 cols (128), ty: 10 rows (160)

    u64 acc[10][4];
#pragma unroll
    for (int i = 0; i < 10; i++)
#pragma unroll
        for (int j = 0; j < 4; j++) acc[i][j] = 0ull;

    float4 a_st[3], b_st[2];
#pragma unroll
    for (int i = 0; i < 3; i++) {
        int idx = tid + i * 256;
        if (idx < 640) {
            int m = idx >> 2, kq = (idx & 3) * 4;
            a_st[i] = *(const float4*)(g_Edge + (size_t)(row0 + m) * 256 + kq);
        }
    }
#pragma unroll
    for (int i = 0; i < 2; i++) {
        int idx = tid + i * 256;
        int n = idx >> 2, kq = (idx & 3) * 4;
        b_st[i] = *(const float4*)(We + (size_t)(col0 + n) * 256 + kq);
    }

    for (int kk = 0; kk < 256; kk += 16) {
        __syncthreads();
#pragma unroll
        for (int i = 0; i < 3; i++) {
            int idx = tid + i * 256;
            if (idx < 640) {
                int m = idx >> 2, kq = (idx & 3) * 4;
                As[kq + 0][m] = a_st[i].x; As[kq + 1][m] = a_st[i].y;
                As[kq + 2][m] = a_st[i].z; As[kq + 3][m] = a_st[i].w;
            }
        }
#pragma unroll
        for (int i = 0; i < 2; i++) {
            int idx = tid + i * 256;
            int n = idx >> 2, kq = (idx & 3) * 4;
            Bs[kq + 0][n] = b_st[i].x; Bs[kq + 1][n] = b_st[i].y;
            Bs[kq + 2][n] = b_st[i].z; Bs[kq + 3][n] = b_st[i].w;
        }
        __syncthreads();

        int kn = kk + 16;
        if (kn < 256) {
#pragma unroll
            for (int i = 0; i < 3; i++) {
                int idx = tid + i * 256;
                if (idx < 640) {
                    int m = idx >> 2, kq = (idx & 3) * 4;
                    a_st[i] = *(const float4*)(g_Edge + (size_t)(row0 + m) * 256 + kn + kq);
                }
            }
#pragma unroll
            for (int i = 0; i < 2; i++) {
                int idx = tid + i * 256;
                int n = idx >> 2, kq = (idx & 3) * 4;
                b_st[i] = *(const float4*)(We + (size_t)(col0 + n) * 256 + kn + kq);
            }
        }

#pragma unroll
        for (int p = 0; p < 16; p++) {
            float av[10];
#pragma unroll
            for (int i = 0; i < 10; i += 2) {
                float2 t2 = *(const float2*)&As[p][ty * 10 + i];
                av[i] = t2.x; av[i + 1] = t2.y;
            }
            const ulonglong2* bp = (const ulonglong2*)&Bs[p][tx * 8];
            ulonglong2 tb0 = bp[0], tb1 = bp[1];
            u64 bb[4] = {tb0.x, tb0.y, tb1.x, tb1.y};
#pragma unroll
            for (int i = 0; i < 10; i++) {
                u64 aa = pack2(av[i], av[i]);
#pragma unroll
                for (int j = 0; j < 4; j++) FMA2(acc[i][j], aa, bb[j]);
            }
        }
    }

#pragma unroll
    for (int grp = 0; grp < 2; grp++) {
        int gr = row0 + ty * 10 + grp * 5;
        int b = gr / 5;
        float mx[8];
#pragma unroll
        for (int c = 0; c < 8; c++) mx[c] = 0.f;
#pragma unroll
        for (int i = 0; i < 5; i++) {
#pragma unroll
            for (int j = 0; j < 4; j++) {
                float2 f = unpack2(acc[grp * 5 + i][j]);
                mx[2 * j]     = fmaxf(mx[2 * j],     f.x);
                mx[2 * j + 1] = fmaxf(mx[2 * j + 1], f.y);
            }
        }
        const float* e4 = g_Edge + (size_t)(gr + 4) * 256 + col0 + tx * 8;
        float4 e0 = *(const float4*)(e4);
        float4 e1 = *(const float4*)(e4 + 4);
        float q[8];
        q[0] = fmaxf(e0.x + mx[0], 0.f); q[1] = fmaxf(e0.y + mx[1], 0.f);
        q[2] = fmaxf(e0.z + mx[2], 0.f); q[3] = fmaxf(e0.w + mx[3], 0.f);
        q[4] = fmaxf(e1.x + mx[4], 0.f); q[5] = fmaxf(e1.y + mx[5], 0.f);
        q[6] = fmaxf(e1.z + mx[6], 0.f); q[7] = fmaxf(e1.w + mx[7], 0.f);
        float* o = g_qt + (size_t)b * 256 + col0 + tx * 8;
        *(float4*)(o)     = make_float4(q[0], q[1], q[2], q[3]);
        *(float4*)(o + 4) = make_float4(q[4], q[5], q[6], q[7]);
    }
}

// ---------------- inp = qt @ W_in^T + b_in (R8 + direct-B) ----------------
__global__ void __launch_bounds__(256) k_inp(const float* __restrict__ Wi,
                                             const float* __restrict__ bi) {
    const int row0 = blockIdx.x * 128;
    const int col0 = blockIdx.y * 128;
    __shared__ __align__(16) float As[16][132];
    __shared__ __align__(16) float Bs[16][132];
    const int tid = threadIdx.x;
    const int tx = tid & 15, ty = tid >> 4;

    u64 acc[8][4];
#pragma unroll
    for (int i = 0; i < 8; i++)
#pragma unroll
        for (int j = 0; j < 4; j++) acc[i][j] = 0ull;

    float4 a_st[2], b_st[2];
#pragma unroll
    for (int i = 0; i < 2; i++) {
        int idx = tid + i * 256;
        int m = idx >> 2, kq = (idx & 3) * 4;
        a_st[i] = *(const float4*)(g_qt + (size_t)(row0 + m) * 256 + kq);
        b_st[i] = *(const float4*)(Wi + (size_t)(col0 + m) * 256 + kq);
    }

    for (int kk = 0; kk < 256; kk += 16) {
        __syncthreads();
#pragma unroll
        for (int i = 0; i < 2; i++) {
            int idx = tid + i * 256;
            int m = idx >> 2, kq = (idx & 3) * 4;
            As[kq + 0][m] = a_st[i].x; As[kq + 1][m] = a_st[i].y;
            As[kq + 2][m] = a_st[i].z; As[kq + 3][m] = a_st[i].w;
            Bs[kq + 0][m] = b_st[i].x; Bs[kq + 1][m] = b_st[i].y;
            Bs[kq + 2][m] = b_st[i].z; Bs[kq + 3][m] = b_st[i].w;
        }
        __syncthreads();

        int kn = kk + 16;
        if (kn < 256) {
#pragma unroll
            for (int i = 0; i < 2; i++) {
                int idx = tid + i * 256;
                int m = idx >> 2, kq = (idx & 3) * 4;
                a_st[i] = *(const float4*)(g_qt + (size_t)(row0 + m) * 256 + kn + kq);
                b_st[i] = *(const float4*)(Wi + (size_t)(col0 + m) * 256 + kn + kq);
            }
        }

#pragma unroll
        for (int p = 0; p < 16; p++) {
            float4 a0 = *(const float4*)&As[p][ty * 8];
            float4 a1 = *(const float4*)&As[p][ty * 8 + 4];
            const ulonglong2* bp = (const ulonglong2*)&Bs[p][tx * 8];
            ulonglong2 tb0 = bp[0], tb1 = bp[1];
            u64 bb[4] = {tb0.x, tb0.y, tb1.x, tb1.y};
            float av[8] = {a0.x, a0.y, a0.z, a0.w, a1.x, a1.y, a1.z, a1.w};
#pragma unroll
            for (int i = 0; i < 8; i++) {
                u64 aa = pack2(av[i], av[i]);
#pragma unroll
                for (int j = 0; j < 4; j++) FMA2(acc[i][j], aa, bb[j]);
            }
        }
    }

#pragma unroll
    for (int i = 0; i < 8; i++) {
        int r = row0 + ty * 8 + i;
        float c[8];
#pragma unroll
        for (int j = 0; j < 4; j++) {
            float2 f = unpack2(acc[i][j]);
            c[2 * j] = f.x; c[2 * j + 1] = f.y;
        }
        const float* bp2 = bi + col0 + tx * 8;
#pragma unroll
        for (int j = 0; j < 8; j++) c[j] += bp2[j];
        float* o = g_inp + (size_t)r * 256 + col0 + tx * 8;
        *(float4*)(o)     = make_float4(c[0], c[1], c[2], c[3]);
        *(float4*)(o + 4) = make_float4(c[4], c[5], c[6], c[7]);
    }
}

// ---------------- ctx GEMM fused with att2: dup-A broadcast, 16x8 ---------
__global__ void __launch_bounds__(256, 1) k_ctx(const float* __restrict__ A,
                                                const float* __restrict__ W,
                                                const float* __restrict__ bias,
                                                const float* __restrict__ Vv,
                                                const int* __restrict__ mask) {
    const int row0 = blockIdx.x * 128;
    __shared__ __align__(16) u64   As2[16][130];
    __shared__ __align__(16) float Bs[16][260];
    const int tid = threadIdx.x;
    const int tx = tid & 31, ty = tid >> 5;
    const int r0 = tid >> 2, ak = (tid & 3) * 4;

    u64 acc[16][4];
#pragma unroll
    for (int i = 0; i < 16; i++)
#pragma unroll
        for (int j = 0; j < 4; j++) acc[i][j] = 0ull;

    float4 a_st0 = *(const float4*)(A + (size_t)(row0 + r0) * 256 + ak);
    float4 a_st1 = *(const float4*)(A + (size_t)(row0 + r0 + 64) * 256 + ak);
    float4 b_st[4];
#pragma unroll
    for (int j = 0; j < 4; j++)
        b_st[j] = *(const float4*)(W + (size_t)(r0 + j * 64) * 256 + ak);

    for (int kk = 0; kk < 256; kk += 16) {
        __syncthreads();
        As2[ak + 0][r0] = pack2(a_st0.x, a_st0.x);
        As2[ak + 1][r0] = pack2(a_st0.y, a_st0.y);
        As2[ak + 2][r0] = pack2(a_st0.z, a_st0.z);
        As2[ak + 3][r0] = pack2(a_st0.w, a_st0.w);
        As2[ak + 0][r0 + 64] = pack2(a_st1.x, a_st1.x);
        As2[ak + 1][r0 + 64] = pack2(a_st1.y, a_st1.y);
        As2[ak + 2][r0 + 64] = pack2(a_st1.z, a_st1.z);
        As2[ak + 3][r0 + 64] = pack2(a_st1.w, a_st1.w);
#pragma unroll
        for (int j = 0; j < 4; j++) {
            int n = r0 + j * 64;
            Bs[ak + 0][n] = b_st[j].x; Bs[ak + 1][n] = b_st[j].y;
            Bs[ak + 2][n] = b_st[j].z; Bs[ak + 3][n] = b_st[j].w;
        }
        __syncthreads();

        int kn = kk + 16;
        if (kn < 256) {
            a_st0 = *(const float4*)(A + (size_t)(row0 + r0) * 256 + kn + ak);
            a_st1 = *(const float4*)(A + (size_t)(row0 + r0 + 64) * 256 + kn + ak);
#pragma unroll
            for (int j = 0; j < 4; j++)
                b_st[j] = *(const float4*)(W + (size_t)(r0 + j * 64) * 256 + kn + ak);
        }

#pragma unroll
        for (int p = 0; p < 16; p++) {
            const ulonglong2* ap = (const ulonglong2*)&As2[p][ty * 16];
            u64 aa[16];
#pragma unroll
            for (int i = 0; i < 8; i++) {
                ulonglong2 t = ap[i];
                aa[2 * i] = t.x; aa[2 * i + 1] = t.y;
            }
            const ulonglong2* bp = (const ulonglong2*)&Bs[p][tx * 8];
            ulonglong2 tb0 = bp[0], tb1 = bp[1];
            u64 bb[4] = {tb0.x, tb0.y, tb1.x, tb1.y};
#pragma unroll
            for (int i = 0; i < 16; i++)
#pragma unroll
                for (int j = 0; j < 4; j++) FMA2(acc[i][j], aa[i], bb[j]);
        }
    }

    float bc[8], vv[8];
#pragma unroll
    for (int j = 0; j < 8; j++) { bc[j] = bias[tx * 8 + j]; vv[j] = Vv[tx * 8 + j]; }

#pragma unroll
    for (int i = 0; i < 16; i++) {
        int m = row0 + ty * 16 + i;
        int b = m / Ll;
        const float* ip = g_inp + (size_t)b * 256 + tx * 8;
        float s = 0.f;
#pragma unroll
        for (int j = 0; j < 4; j++) {
            float2 cf = unpack2(acc[i][j]);
            int jj = 2 * j;
            s += vv[jj]     * tanhf(ip[jj]     + (cf.x + bc[jj]));
            s += vv[jj + 1] * tanhf(ip[jj + 1] + (cf.y + bc[jj + 1]));
        }
#pragma unroll
        for (int o = 16; o > 0; o >>= 1) s += __shfl_xor_sync(0xffffffffu, s, o);
        if (tx == 0) {
            if (mask[m] == 0) s = -1000000000.0f;
            g_att2[m] = 10.0f * tanhf(s);
        }
    }
}

// ---------------- per-column softmax stats over batch axis ----------------
__global__ void k_colred() {
    const int l = blockIdx.x;
    __shared__ float red[256];
    float mx = __int_as_float(0xff800000);
    for (int b = threadIdx.x; b < Bb; b += 256) mx = fmaxf(mx, g_att2[b * Ll + l]);
    red[threadIdx.x] = mx; __syncthreads();
    for (int o = 128; o > 0; o >>= 1) {
        if (threadIdx.x < o) red[threadIdx.x] = fmaxf(red[threadIdx.x], red[threadIdx.x + o]);
        __syncthreads();
    }
    mx = red[0]; __syncthreads();
    float sum = 0.f;
    for (int b = threadIdx.x; b < Bb; b += 256) sum += expf(g_att2[b * Ll + l] - mx);
    red[threadIdx.x] = sum; __syncthreads();
    for (int o = 128; o > 0; o >>= 1) {
        if (threadIdx.x < o) red[threadIdx.x] += red[threadIdx.x + o];
        __syncthreads();
    }
    if (threadIdx.x == 0) {
        g_colmax[l] = mx;
        g_colsum[l] = red[0];
        g_logZ[l]   = mx + logf(red[0]);
    }
}

// ---------------- Gumbel-argmax + p + new_mask ----------------------------
__global__ void k_final(const int* __restrict__ mask, float* __restrict__ out) {
    int b = blockIdx.x * blockDim.x + threadIdx.x;
    if (b >= Bb) return;
    const float TINY = 1.17549435e-38f;
    float best = __int_as_float(0xff800000);
    int idx = 0;
    float a2[Ll];
#pragma unroll
    for (int l = 0; l < Ll; l++) {
        float a = g_att2[b * Ll + l];
        a2[l] = a;
        float la = a - g_logZ[l];
        uint32_t bits = jax_bits((uint32_t)(b * Ll + l));
        float fl = __uint_as_float((bits >> 9) | 0x3F800000u) - 1.0f;
        float u  = fmaxf(TINY, fl + TINY);
        float g  = -logf(-logf(u));
        float s  = la + g;
        if (s > best) { best = s; idx = l; }
    }
    float p = expf(a2[idx] - g_colmax[idx]) / g_colsum[idx];
    out[b]      = (float)idx;
    out[Bb + b] = p;
#pragma unroll
    for (int l = 0; l < Ll; l++)
        out[2 * Bb + b * Ll + l] = (float)(mask[b * Ll + l] - (l == idx ? 1 : 0));
}

// ---------------- launcher ----------------
extern "C" void kernel_launch(void* const* d_in, const int* in_sizes, int n_in,
                              void* d_out, int out_size) {
    const float* enc    = (const float*)d_in[0];
    const int*   xes    = (const int*)  d_in[1];
    const int*   mask   = (const int*)  d_in[2];
    const float* W_h    = (const float*)d_in[3];
    const float* W_v    = (const float*)d_in[4];
    const float* Ws_h   = (const float*)d_in[5];
    const float* Ws_v   = (const float*)d_in[6];
    const float* W_edge = (const float*)d_in[7];
    const float* W_in   = (const float*)d_in[8];
    const float* b_in   = (const float*)d_in[9];
    const float* W_ctx  = (const float*)d_in[10];
    const float* b_ctx  = (const float*)d_in[11];
    const float* Vv     = (const float*)d_in[12];
    float* out = (float*)d_out;

    k_init<<<1, 1>>>();
    k_detect<<<1, 128>>>(xes);
    k_map<<<(MROWS + 255) / 256, 256>>>(xes);

    k_edges<<<MROWS / 128, 256>>>(enc, W_h, W_v, Ws_h, Ws_v);
    k_subq<<<dim3(MROWS / 160, 2), 256>>>(W_edge);
    k_inp<<<dim3(Bb / 128, 2), 256>>>(W_in, b_in);
    k_ctx<<<MCTX / 128, 256>>>(enc, W_ctx, b_ctx, Vv, mask);
    k_colred<<<Ll, 256>>>();
    k_final<<<(Bb + 255) / 256, 256>>>(mask, out);
}